// round 1
// baseline (speedup 1.0000x reference)
#include <cuda_runtime.h>
#include <math.h>

// Problem constants (fixed shapes from reference):
// B=4, N=128, T=128 -> NTOK = 65536 tokens, DIM = 256, H = 8, hd = 32.
#define NTOK 65536
#define DIM  256

// Scratch (no allocations allowed; __device__ globals are the sanctioned path).
__device__ float g_q [NTOK * DIM];
__device__ float g_k [NTOK * DIM];
__device__ float g_vv[NTOK * DIM];
__device__ float g_x [NTOK * DIM];

// ---------------------------------------------------------------------------
// Kernel 1: fused QKV projection.  Q/K/V = A @ Wq/Wk/Wv, A = [65536,256].
// 64x64 output tile per block, K looped in 16-chunks, 4x4 per-thread microtile
// for each of the 3 outputs (A smem tile amortized 3x).
// ---------------------------------------------------------------------------
__global__ __launch_bounds__(256, 2)
void qkv_kernel(const float* __restrict__ A,
                const float* __restrict__ Wq,
                const float* __restrict__ Wk,
                const float* __restrict__ Wv)
{
    __shared__ __align__(16) float As[64][16];
    __shared__ __align__(16) float Bq[16][64];
    __shared__ __align__(16) float Bk[16][64];
    __shared__ __align__(16) float Bv[16][64];

    const int tid = threadIdx.x;
    const int tx  = tid & 15;        // 0..15  -> 4-col group
    const int ty  = tid >> 4;        // 0..15  -> 4-row group
    const int rowBase = blockIdx.x * 64;
    const int colBase = blockIdx.y * 64;

    float aq[16], ak[16], av[16];
#pragma unroll
    for (int i = 0; i < 16; i++) { aq[i] = 0.f; ak[i] = 0.f; av[i] = 0.f; }

    for (int k0 = 0; k0 < DIM; k0 += 16) {
        // Load A tile: 64 rows x 16 k (coalesced 64B/row-chunk).
        {
            const int c  = tid & 15;
            const int r0 = tid >> 4;
#pragma unroll
            for (int j = 0; j < 4; j++) {
                const int r = r0 + j * 16;
                As[r][c] = A[(rowBase + r) * DIM + k0 + c];
            }
        }
        // Load the three B tiles: 16 k x 64 cols (fully coalesced).
        {
            const int c  = tid & 63;
            const int r0 = tid >> 6;
#pragma unroll
            for (int j = 0; j < 4; j++) {
                const int r = r0 + j * 4;
                const int g = (k0 + r) * DIM + colBase + c;
                Bq[r][c] = Wq[g];
                Bk[r][c] = Wk[g];
                Bv[r][c] = Wv[g];
            }
        }
        __syncthreads();

#pragma unroll
        for (int kk = 0; kk < 16; kk++) {
            float a[4];
#pragma unroll
            for (int i = 0; i < 4; i++) a[i] = As[ty * 4 + i][kk];

            const float4 q4 = *reinterpret_cast<const float4*>(&Bq[kk][tx * 4]);
            const float4 k4 = *reinterpret_cast<const float4*>(&Bk[kk][tx * 4]);
            const float4 v4 = *reinterpret_cast<const float4*>(&Bv[kk][tx * 4]);
            const float bq[4] = {q4.x, q4.y, q4.z, q4.w};
            const float bk[4] = {k4.x, k4.y, k4.z, k4.w};
            const float bv[4] = {v4.x, v4.y, v4.z, v4.w};

#pragma unroll
            for (int i = 0; i < 4; i++)
#pragma unroll
                for (int j = 0; j < 4; j++) {
                    aq[i * 4 + j] += a[i] * bq[j];
                    ak[i * 4 + j] += a[i] * bk[j];
                    av[i * 4 + j] += a[i] * bv[j];
                }
        }
        __syncthreads();
    }

#pragma unroll
    for (int i = 0; i < 4; i++) {
        const int row = rowBase + ty * 4 + i;
        const int col = colBase + tx * 4;
        float4 o;
        o = make_float4(aq[i*4+0], aq[i*4+1], aq[i*4+2], aq[i*4+3]);
        *reinterpret_cast<float4*>(&g_q [row * DIM + col]) = o;
        o = make_float4(ak[i*4+0], ak[i*4+1], ak[i*4+2], ak[i*4+3]);
        *reinterpret_cast<float4*>(&g_k [row * DIM + col]) = o;
        o = make_float4(av[i*4+0], av[i*4+1], av[i*4+2], av[i*4+3]);
        *reinterpret_cast<float4*>(&g_vv[row * DIM + col]) = o;
    }
}

// ---------------------------------------------------------------------------
// Kernel 2: per-token attention over the HEADS axis.
// One warp per token.  Lane d holds q/k/v[h][d] for all 8 heads.
// S[h][g] via warp allreduce, online softmax over g, x[h][d] accumulated.
// ---------------------------------------------------------------------------
__global__ __launch_bounds__(256)
void attn_kernel()
{
    const int warp = threadIdx.x >> 5;
    const int lane = threadIdx.x & 31;
    const int token = blockIdx.x * 8 + warp;

    const float* __restrict__ q = g_q  + token * DIM;
    const float* __restrict__ k = g_k  + token * DIM;
    const float* __restrict__ v = g_vv + token * DIM;
    float* __restrict__ x       = g_x  + token * DIM;

    float qr[8], kr[8], vr[8];
#pragma unroll
    for (int h = 0; h < 8; h++) {
        qr[h] = q[h * 32 + lane];
        kr[h] = k[h * 32 + lane];
        vr[h] = v[h * 32 + lane];
    }

    const float scale = 0.17677669529663687f;   // 32^-0.5

#pragma unroll
    for (int h = 0; h < 8; h++) {
        float m = -3.0e38f, l = 0.f, acc = 0.f;
#pragma unroll
        for (int g = 0; g < 8; g++) {
            float s = qr[h] * kr[g];
#pragma unroll
            for (int o = 16; o > 0; o >>= 1)
                s += __shfl_xor_sync(0xffffffffu, s, o);
            s *= scale;
            const float mn   = fmaxf(m, s);
            const float corr = __expf(m - mn);
            const float e    = __expf(s - mn);
            acc = acc * corr + e * vr[g];
            l   = l   * corr + e;
            m   = mn;
        }
        x[h * 32 + lane] = acc / l;
    }
}

// ---------------------------------------------------------------------------
// Kernel 3: output projection with bias.  out = X @ Wp + bp.
// Same tiling as kernel 1, single output matrix.
// ---------------------------------------------------------------------------
__global__ __launch_bounds__(256, 2)
void proj_kernel(const float* __restrict__ Wp,
                 const float* __restrict__ bp,
                 float* __restrict__ out)
{
    __shared__ __align__(16) float As[64][16];
    __shared__ __align__(16) float Bs[16][64];

    const int tid = threadIdx.x;
    const int tx  = tid & 15;
    const int ty  = tid >> 4;
    const int rowBase = blockIdx.x * 64;
    const int colBase = blockIdx.y * 64;

    float acc[16];
#pragma unroll
    for (int i = 0; i < 16; i++) acc[i] = 0.f;

    for (int k0 = 0; k0 < DIM; k0 += 16) {
        {
            const int c  = tid & 15;
            const int r0 = tid >> 4;
#pragma unroll
            for (int j = 0; j < 4; j++) {
                const int r = r0 + j * 16;
                As[r][c] = g_x[(rowBase + r) * DIM + k0 + c];
            }
        }
        {
            const int c  = tid & 63;
            const int r0 = tid >> 6;
#pragma unroll
            for (int j = 0; j < 4; j++) {
                const int r = r0 + j * 4;
                Bs[r][c] = Wp[(k0 + r) * DIM + colBase + c];
            }
        }
        __syncthreads();

#pragma unroll
        for (int kk = 0; kk < 16; kk++) {
            float a[4];
#pragma unroll
            for (int i = 0; i < 4; i++) a[i] = As[ty * 4 + i][kk];
            const float4 b4 = *reinterpret_cast<const float4*>(&Bs[kk][tx * 4]);
            const float b[4] = {b4.x, b4.y, b4.z, b4.w};
#pragma unroll
            for (int i = 0; i < 4; i++)
#pragma unroll
                for (int j = 0; j < 4; j++)
                    acc[i * 4 + j] += a[i] * b[j];
        }
        __syncthreads();
    }

    const float4 bias4 = *reinterpret_cast<const float4*>(&bp[colBase + tx * 4]);
    const float bias[4] = {bias4.x, bias4.y, bias4.z, bias4.w};

#pragma unroll
    for (int i = 0; i < 4; i++) {
        const int row = rowBase + ty * 4 + i;
        const int col = colBase + tx * 4;
        const float4 o = make_float4(acc[i*4+0] + bias[0],
                                     acc[i*4+1] + bias[1],
                                     acc[i*4+2] + bias[2],
                                     acc[i*4+3] + bias[3]);
        *reinterpret_cast<float4*>(&out[row * DIM + col]) = o;
    }
}

// ---------------------------------------------------------------------------
extern "C" void kernel_launch(void* const* d_in, const int* in_sizes, int n_in,
                              void* d_out, int out_size)
{
    const float* v  = (const float*)d_in[0];   // [4,128,128,256] -> [65536,256]
    const float* Wq = (const float*)d_in[1];
    const float* Wk = (const float*)d_in[2];
    const float* Wv = (const float*)d_in[3];
    const float* Wp = (const float*)d_in[4];
    const float* bp = (const float*)d_in[5];
    float* out = (float*)d_out;

    dim3 gemm_grid(NTOK / 64, DIM / 64);   // (1024, 4)
    qkv_kernel<<<gemm_grid, 256>>>(v, Wq, Wk, Wv);
    attn_kernel<<<NTOK / 8, 256>>>();
    proj_kernel<<<gemm_grid, 256>>>(Wp, bp, out);
}

// round 2
// speedup vs baseline: 1.3414x; 1.3414x over previous
#include <cuda_runtime.h>
#include <cuda_bf16.h>
#include <math.h>

// Shapes: B=4,N=128,T=128 -> NTOK=65536 tokens, DIM=256, H=8, hd=32.
#define NTOK 65536
#define DIM  256

#define KCHUNK 32            // K elements per smem stage
#define AS_STRIDE 34         // u32 words per A row: 16 pairs * 2 (hi,lo) + 2 pad
#define BS_STRIDE 34         // u32 words per B col slice (same layout along K)

// Scratch
__device__ float g_q [NTOK * DIM];
__device__ float g_k [NTOK * DIM];
__device__ float g_vv[NTOK * DIM];
__device__ float g_x [NTOK * DIM];

__device__ __forceinline__ unsigned pack_hi(float a, float b) {
    __nv_bfloat162 t = __floats2bfloat162_rn(a, b);
    return *reinterpret_cast<unsigned*>(&t);
}
__device__ __forceinline__ void split2(float a, float b, unsigned& hi, unsigned& lo) {
    __nv_bfloat16 ha = __float2bfloat16_rn(a);
    __nv_bfloat16 hb = __float2bfloat16_rn(b);
    float ra = a - __bfloat162float(ha);
    float rb = b - __bfloat162float(hb);
    __nv_bfloat162 th; th.x = ha; th.y = hb;
    hi = *reinterpret_cast<unsigned*>(&th);
    lo = pack_hi(ra, rb);
}

__device__ __forceinline__ void mma_bf16(float& c0, float& c1, float& c2, float& c3,
                                         unsigned a0, unsigned a1, unsigned a2, unsigned a3,
                                         unsigned b0, unsigned b1) {
    asm volatile(
        "mma.sync.aligned.m16n8k16.row.col.f32.bf16.bf16.f32 "
        "{%0,%1,%2,%3}, {%4,%5,%6,%7}, {%8,%9}, {%0,%1,%2,%3};\n"
        : "+f"(c0), "+f"(c1), "+f"(c2), "+f"(c3)
        : "r"(a0), "r"(a1), "r"(a2), "r"(a3), "r"(b0), "r"(b1));
}

// ---------------------------------------------------------------------------
// Kernel 1: fused QKV GEMM, tensor cores, bf16 3-pass split.
// Block tile M=128 N=64, 8 warps (4M x 2N), warp tile 32x32.
// ---------------------------------------------------------------------------
__global__ __launch_bounds__(256, 1)
void qkv_kernel(const float* __restrict__ A,
                const float* __restrict__ Wq,
                const float* __restrict__ Wk,
                const float* __restrict__ Wv)
{
    __shared__ __align__(16) unsigned As[128 * AS_STRIDE];       // 17408 B
    __shared__ __align__(16) unsigned Bs[3][64 * BS_STRIDE];     // 3 * 8704 B

    const int tid  = threadIdx.x;
    const int warp = tid >> 5;
    const int lane = tid & 31;
    const int gr   = lane >> 2;   // 0..7
    const int qc   = lane & 3;    // 0..3
    const int warpM = (warp >> 1) * 32;
    const int warpN = (warp & 1) * 32;
    const int rowBase = blockIdx.x * 128;
    const int colBase = blockIdx.y * 64;

    const float* Ws[3] = {Wq, Wk, Wv};

    float acc[3][2][4][4];
#pragma unroll
    for (int w = 0; w < 3; w++)
#pragma unroll
        for (int mt = 0; mt < 2; mt++)
#pragma unroll
            for (int nt = 0; nt < 4; nt++)
#pragma unroll
                for (int i = 0; i < 4; i++) acc[w][mt][nt][i] = 0.f;

    for (int k0 = 0; k0 < DIM; k0 += KCHUNK) {
        // ---- stage A: 128 rows x 32 k -> hi/lo bf16 pairs
        {
            const float* Abase = A + (size_t)rowBase * DIM + k0;
#pragma unroll
            for (int it = 0; it < 4; it++) {
                const int idx = tid + it * 256;         // 0..1023
                const int row = idx >> 3;
                const int c4  = idx & 7;                // float4 index (k = c4*4)
                const float4 x = *reinterpret_cast<const float4*>(Abase + row * DIM + c4 * 4);
                unsigned h0, l0, h1, l1;
                split2(x.x, x.y, h0, l0);
                split2(x.z, x.w, h1, l1);
                const int base = row * AS_STRIDE + c4 * 4;  // pair p = c4*2 -> word p*2
                As[base + 0] = h0; As[base + 1] = l0;
                As[base + 2] = h1; As[base + 3] = l1;
            }
        }
        // ---- stage B (x3 weights): 32 k x 64 n, stored [n][kpair]{hi,lo}
#pragma unroll
        for (int w = 0; w < 3; w++) {
            const float* W = Ws[w];
#pragma unroll
            for (int it = 0; it < 4; it++) {
                const int idx = tid + it * 256;         // 0..1023
                const int n  = idx & 63;
                const int p  = idx >> 6;                // 0..15 pair index
                const float b0 = W[(size_t)(k0 + 2 * p    ) * DIM + colBase + n];
                const float b1 = W[(size_t)(k0 + 2 * p + 1) * DIM + colBase + n];
                unsigned h, l;
                split2(b0, b1, h, l);
                const int base = n * BS_STRIDE + p * 2;
                Bs[w][base] = h; Bs[w][base + 1] = l;
            }
        }
        __syncthreads();

        // ---- compute: 2 K-steps of 16
#pragma unroll
        for (int ks = 0; ks < 2; ks++) {
            const int kb = ks * 8;  // pair base for this K16 step
            unsigned ah[2][4], al[2][4];
#pragma unroll
            for (int mt = 0; mt < 2; mt++) {
                const int r = warpM + mt * 16 + gr;
                uint2 v;
                v = *reinterpret_cast<const uint2*>(&As[ r      * AS_STRIDE + (kb + qc    ) * 2]);
                ah[mt][0] = v.x; al[mt][0] = v.y;
                v = *reinterpret_cast<const uint2*>(&As[(r + 8) * AS_STRIDE + (kb + qc    ) * 2]);
                ah[mt][1] = v.x; al[mt][1] = v.y;
                v = *reinterpret_cast<const uint2*>(&As[ r      * AS_STRIDE + (kb + qc + 4) * 2]);
                ah[mt][2] = v.x; al[mt][2] = v.y;
                v = *reinterpret_cast<const uint2*>(&As[(r + 8) * AS_STRIDE + (kb + qc + 4) * 2]);
                ah[mt][3] = v.x; al[mt][3] = v.y;
            }
#pragma unroll
            for (int w = 0; w < 3; w++) {
#pragma unroll
                for (int nt = 0; nt < 4; nt++) {
                    const int n = warpN + nt * 8 + gr;
                    uint2 v0 = *reinterpret_cast<const uint2*>(&Bs[w][n * BS_STRIDE + (kb + qc    ) * 2]);
                    uint2 v1 = *reinterpret_cast<const uint2*>(&Bs[w][n * BS_STRIDE + (kb + qc + 4) * 2]);
                    const unsigned bh0 = v0.x, bl0 = v0.y, bh1 = v1.x, bl1 = v1.y;
#pragma unroll
                    for (int mt = 0; mt < 2; mt++) {
                        float* c = acc[w][mt][nt];
                        // hi*hi
                        mma_bf16(c[0], c[1], c[2], c[3],
                                 ah[mt][0], ah[mt][1], ah[mt][2], ah[mt][3], bh0, bh1);
                        // hi*lo
                        mma_bf16(c[0], c[1], c[2], c[3],
                                 ah[mt][0], ah[mt][1], ah[mt][2], ah[mt][3], bl0, bl1);
                        // lo*hi
                        mma_bf16(c[0], c[1], c[2], c[3],
                                 al[mt][0], al[mt][1], al[mt][2], al[mt][3], bh0, bh1);
                    }
                }
            }
        }
        __syncthreads();
    }

    // ---- epilogue
    float* outs[3] = {g_q, g_k, g_vv};
#pragma unroll
    for (int w = 0; w < 3; w++) {
#pragma unroll
        for (int mt = 0; mt < 2; mt++) {
#pragma unroll
            for (int nt = 0; nt < 4; nt++) {
                const float* c = acc[w][mt][nt];
                const int r   = rowBase + warpM + mt * 16 + gr;
                const int col = colBase + warpN + nt * 8 + qc * 2;
                float2* p0 = reinterpret_cast<float2*>(&outs[w][(size_t) r      * DIM + col]);
                float2* p1 = reinterpret_cast<float2*>(&outs[w][(size_t)(r + 8) * DIM + col]);
                *p0 = make_float2(c[0], c[1]);
                *p1 = make_float2(c[2], c[3]);
            }
        }
    }
}

// ---------------------------------------------------------------------------
// Kernel 2: per-token attention over the HEADS axis (unchanged).
// ---------------------------------------------------------------------------
__global__ __launch_bounds__(256)
void attn_kernel()
{
    const int warp = threadIdx.x >> 5;
    const int lane = threadIdx.x & 31;
    const int token = blockIdx.x * 8 + warp;

    const float* __restrict__ q = g_q  + (size_t)token * DIM;
    const float* __restrict__ k = g_k  + (size_t)token * DIM;
    const float* __restrict__ v = g_vv + (size_t)token * DIM;
    float* __restrict__ x       = g_x  + (size_t)token * DIM;

    float qr[8], kr[8], vr[8];
#pragma unroll
    for (int h = 0; h < 8; h++) {
        qr[h] = q[h * 32 + lane];
        kr[h] = k[h * 32 + lane];
        vr[h] = v[h * 32 + lane];
    }

    const float scale = 0.17677669529663687f;   // 32^-0.5

#pragma unroll
    for (int h = 0; h < 8; h++) {
        float m = -3.0e38f, l = 0.f, acc = 0.f;
#pragma unroll
        for (int g = 0; g < 8; g++) {
            float s = qr[h] * kr[g];
#pragma unroll
            for (int o = 16; o > 0; o >>= 1)
                s += __shfl_xor_sync(0xffffffffu, s, o);
            s *= scale;
            const float mn   = fmaxf(m, s);
            const float corr = __expf(m - mn);
            const float e    = __expf(s - mn);
            acc = acc * corr + e * vr[g];
            l   = l   * corr + e;
            m   = mn;
        }
        x[h * 32 + lane] = acc / l;
    }
}

// ---------------------------------------------------------------------------
// Kernel 3: output projection (tensor cores, bf16 3-pass) + bias.
// ---------------------------------------------------------------------------
__global__ __launch_bounds__(256, 1)
void proj_kernel(const float* __restrict__ Wp,
                 const float* __restrict__ bp,
                 float* __restrict__ out)
{
    __shared__ __align__(16) unsigned As[128 * AS_STRIDE];
    __shared__ __align__(16) unsigned Bs[64 * BS_STRIDE];

    const int tid  = threadIdx.x;
    const int warp = tid >> 5;
    const int lane = tid & 31;
    const int gr   = lane >> 2;
    const int qc   = lane & 3;
    const int warpM = (warp >> 1) * 32;
    const int warpN = (warp & 1) * 32;
    const int rowBase = blockIdx.x * 128;
    const int colBase = blockIdx.y * 64;

    float acc[2][4][4];
#pragma unroll
    for (int mt = 0; mt < 2; mt++)
#pragma unroll
        for (int nt = 0; nt < 4; nt++)
#pragma unroll
            for (int i = 0; i < 4; i++) acc[mt][nt][i] = 0.f;

    for (int k0 = 0; k0 < DIM; k0 += KCHUNK) {
        {
            const float* Abase = g_x + (size_t)rowBase * DIM + k0;
#pragma unroll
            for (int it = 0; it < 4; it++) {
                const int idx = tid + it * 256;
                const int row = idx >> 3;
                const int c4  = idx & 7;
                const float4 x = *reinterpret_cast<const float4*>(Abase + row * DIM + c4 * 4);
                unsigned h0, l0, h1, l1;
                split2(x.x, x.y, h0, l0);
                split2(x.z, x.w, h1, l1);
                const int base = row * AS_STRIDE + c4 * 4;
                As[base + 0] = h0; As[base + 1] = l0;
                As[base + 2] = h1; As[base + 3] = l1;
            }
        }
        {
#pragma unroll
            for (int it = 0; it < 4; it++) {
                const int idx = tid + it * 256;
                const int n  = idx & 63;
                const int p  = idx >> 6;
                const float b0 = Wp[(size_t)(k0 + 2 * p    ) * DIM + colBase + n];
                const float b1 = Wp[(size_t)(k0 + 2 * p + 1) * DIM + colBase + n];
                unsigned h, l;
                split2(b0, b1, h, l);
                const int base = n * BS_STRIDE + p * 2;
                Bs[base] = h; Bs[base + 1] = l;
            }
        }
        __syncthreads();

#pragma unroll
        for (int ks = 0; ks < 2; ks++) {
            const int kb = ks * 8;
            unsigned ah[2][4], al[2][4];
#pragma unroll
            for (int mt = 0; mt < 2; mt++) {
                const int r = warpM + mt * 16 + gr;
                uint2 v;
                v = *reinterpret_cast<const uint2*>(&As[ r      * AS_STRIDE + (kb + qc    ) * 2]);
                ah[mt][0] = v.x; al[mt][0] = v.y;
                v = *reinterpret_cast<const uint2*>(&As[(r + 8) * AS_STRIDE + (kb + qc    ) * 2]);
                ah[mt][1] = v.x; al[mt][1] = v.y;
                v = *reinterpret_cast<const uint2*>(&As[ r      * AS_STRIDE + (kb + qc + 4) * 2]);
                ah[mt][2] = v.x; al[mt][2] = v.y;
                v = *reinterpret_cast<const uint2*>(&As[(r + 8) * AS_STRIDE + (kb + qc + 4) * 2]);
                ah[mt][3] = v.x; al[mt][3] = v.y;
            }
#pragma unroll
            for (int nt = 0; nt < 4; nt++) {
                const int n = warpN + nt * 8 + gr;
                uint2 v0 = *reinterpret_cast<const uint2*>(&Bs[n * BS_STRIDE + (kb + qc    ) * 2]);
                uint2 v1 = *reinterpret_cast<const uint2*>(&Bs[n * BS_STRIDE + (kb + qc + 4) * 2]);
                const unsigned bh0 = v0.x, bl0 = v0.y, bh1 = v1.x, bl1 = v1.y;
#pragma unroll
                for (int mt = 0; mt < 2; mt++) {
                    float* c = acc[mt][nt];
                    mma_bf16(c[0], c[1], c[2], c[3],
                             ah[mt][0], ah[mt][1], ah[mt][2], ah[mt][3], bh0, bh1);
                    mma_bf16(c[0], c[1], c[2], c[3],
                             ah[mt][0], ah[mt][1], ah[mt][2], ah[mt][3], bl0, bl1);
                    mma_bf16(c[0], c[1], c[2], c[3],
                             al[mt][0], al[mt][1], al[mt][2], al[mt][3], bh0, bh1);
                }
            }
        }
        __syncthreads();
    }

#pragma unroll
    for (int mt = 0; mt < 2; mt++) {
#pragma unroll
        for (int nt = 0; nt < 4; nt++) {
            const float* c = acc[mt][nt];
            const int r   = rowBase + warpM + mt * 16 + gr;
            const int col = colBase + warpN + nt * 8 + qc * 2;
            const float bx = bp[col], by = bp[col + 1];
            float2* p0 = reinterpret_cast<float2*>(&out[(size_t) r      * DIM + col]);
            float2* p1 = reinterpret_cast<float2*>(&out[(size_t)(r + 8) * DIM + col]);
            *p0 = make_float2(c[0] + bx, c[1] + by);
            *p1 = make_float2(c[2] + bx, c[3] + by);
        }
    }
}

// ---------------------------------------------------------------------------
extern "C" void kernel_launch(void* const* d_in, const int* in_sizes, int n_in,
                              void* d_out, int out_size)
{
    const float* v  = (const float*)d_in[0];
    const float* Wq = (const float*)d_in[1];
    const float* Wk = (const float*)d_in[2];
    const float* Wv = (const float*)d_in[3];
    const float* Wp = (const float*)d_in[4];
    const float* bp = (const float*)d_in[5];
    float* out = (float*)d_out;

    dim3 gemm_grid(NTOK / 128, DIM / 64);   // (512, 4)
    qkv_kernel<<<gemm_grid, 256>>>(v, Wq, Wk, Wv);
    attn_kernel<<<NTOK / 8, 256>>>();
    proj_kernel<<<gemm_grid, 256>>>(Wp, bp, out);
}

// round 3
// speedup vs baseline: 1.5699x; 1.1704x over previous
#include <cuda_runtime.h>
#include <cuda_bf16.h>
#include <math.h>

// Shapes: B=4,N=128,T=128 -> NTOK=65536 tokens, DIM=256, H=8, hd=32.
#define NTOK 65536
#define DIM  256
#define NCAT 768            // concatenated Q|K|V output width
#define SSTRIDE 40          // bf16 units per smem row (80 bytes) -> conflict-free LDSM

// ---------------- device scratch (no allocations allowed) -------------------
__device__ __nv_bfloat16 g_a_hi[NTOK * DIM];
__device__ __nv_bfloat16 g_a_lo[NTOK * DIM];
__device__ __nv_bfloat16 g_w_hi[NCAT * DIM];     // [n][k] transposed cat(Wq,Wk,Wv)
__device__ __nv_bfloat16 g_w_lo[NCAT * DIM];
__device__ __nv_bfloat16 g_wp_hi[DIM * DIM];     // [n][k] transposed Wp
__device__ __nv_bfloat16 g_wp_lo[DIM * DIM];
__device__ __nv_bfloat16 g_c_hi[(size_t)NTOK * NCAT];   // q|k|v per token
__device__ __nv_bfloat16 g_c_lo[(size_t)NTOK * NCAT];
__device__ __nv_bfloat16 g_x_hi[NTOK * DIM];
__device__ __nv_bfloat16 g_x_lo[NTOK * DIM];

// ---------------- helpers ---------------------------------------------------
__device__ __forceinline__ void ldsm4(unsigned* r, unsigned addr) {
    asm volatile("ldmatrix.sync.aligned.m8n8.x4.shared.b16 {%0,%1,%2,%3}, [%4];"
                 : "=r"(r[0]), "=r"(r[1]), "=r"(r[2]), "=r"(r[3]) : "r"(addr));
}
__device__ __forceinline__ void mma4(float* c, const unsigned* a, unsigned b0, unsigned b1) {
    asm volatile(
        "mma.sync.aligned.m16n8k16.row.col.f32.bf16.bf16.f32 "
        "{%0,%1,%2,%3}, {%4,%5,%6,%7}, {%8,%9}, {%0,%1,%2,%3};\n"
        : "+f"(c[0]), "+f"(c[1]), "+f"(c[2]), "+f"(c[3])
        : "r"(a[0]), "r"(a[1]), "r"(a[2]), "r"(a[3]), "r"(b0), "r"(b1));
}

// ---------------- pre-pass kernels ------------------------------------------
__global__ __launch_bounds__(256)
void split_input_kernel(const float* __restrict__ v)
{
    const int i = blockIdx.x * 256 + threadIdx.x;         // float4 index
    const float4 x = reinterpret_cast<const float4*>(v)[i];
    __nv_bfloat162 h0 = __floats2bfloat162_rn(x.x, x.y);
    __nv_bfloat162 h1 = __floats2bfloat162_rn(x.z, x.w);
    __nv_bfloat162 l0 = __floats2bfloat162_rn(x.x - __bfloat162float(h0.x),
                                              x.y - __bfloat162float(h0.y));
    __nv_bfloat162 l1 = __floats2bfloat162_rn(x.z - __bfloat162float(h1.x),
                                              x.w - __bfloat162float(h1.y));
    reinterpret_cast<__nv_bfloat162*>(g_a_hi)[i * 2 + 0] = h0;
    reinterpret_cast<__nv_bfloat162*>(g_a_hi)[i * 2 + 1] = h1;
    reinterpret_cast<__nv_bfloat162*>(g_a_lo)[i * 2 + 0] = l0;
    reinterpret_cast<__nv_bfloat162*>(g_a_lo)[i * 2 + 1] = l1;
}

// W is [k][c] row-major (256x256).  Writes out[n=c][k] split into hi/lo.
__global__ __launch_bounds__(256)
void transpose_split_kernel(const float* __restrict__ W, int which)
{
    __shared__ float tile[32][33];
    const int tx = threadIdx.x, ty = threadIdx.y;
    const int bx = blockIdx.x, by = blockIdx.y;
#pragma unroll
    for (int j = 0; j < 32; j += 8)
        tile[ty + j][tx] = W[(by * 32 + ty + j) * DIM + bx * 32 + tx];
    __syncthreads();
    __nv_bfloat16* ohi = (which < 3) ? (g_w_hi + which * DIM * DIM) : g_wp_hi;
    __nv_bfloat16* olo = (which < 3) ? (g_w_lo + which * DIM * DIM) : g_wp_lo;
#pragma unroll
    for (int j = 0; j < 32; j += 8) {
        const float val = tile[tx][ty + j];
        const int n = bx * 32 + ty + j;
        const int k = by * 32 + tx;
        const __nv_bfloat16 hb = __float2bfloat16_rn(val);
        ohi[n * DIM + k] = hb;
        olo[n * DIM + k] = __float2bfloat16_rn(val - __bfloat162float(hb));
    }
}

// ---------------- main GEMM (bf16 3-pass, ldmatrix + mma) -------------------
// Block tile 128(M) x 128(N), 8 warps as 4M x 2N, warp tile 32x64.
// ONC: output row stride (768 for QKV-cat, 256 for proj).
template<int ONC, bool IS_PROJ>
__global__ __launch_bounds__(256, 1)
void gemm_kernel(const __nv_bfloat16* __restrict__ Ahi,
                 const __nv_bfloat16* __restrict__ Alo,
                 const __nv_bfloat16* __restrict__ Bhi,
                 const __nv_bfloat16* __restrict__ Blo,
                 const float* __restrict__ bias,
                 float* __restrict__ outF)
{
    __shared__ __align__(16) __nv_bfloat16 As[2][128 * SSTRIDE];   // hi, lo
    __shared__ __align__(16) __nv_bfloat16 Bs[2][128 * SSTRIDE];

    const int tid  = threadIdx.x;
    const int warp = tid >> 5;
    const int lane = tid & 31;
    const int lane15 = lane & 15;
    const int laneHi = lane >> 4;
    const int gr = lane >> 2;
    const int qc = lane & 3;
    const int warpM = (warp >> 1) * 32;
    const int warpN = (warp & 1) * 64;
    const int rowBase = blockIdx.x * 128;
    const int colBase = blockIdx.y * 128;

    const unsigned sA = (unsigned)__cvta_generic_to_shared(&As[0][0]);
    const unsigned sB = (unsigned)__cvta_generic_to_shared(&Bs[0][0]);
    const unsigned LOOFF = 128 * SSTRIDE * 2;   // bytes from hi plane to lo plane
    const unsigned aBase = sA + (warpM + lane15) * 80 + laneHi * 16;
    const unsigned bBase = sB + (warpN + lane15) * 80 + laneHi * 16;

    // staging indices: 512 (row,chunk) pairs, 2 per thread
    const int r0i = (tid + 0)   >> 2, c0i = (tid + 0)   & 3;
    const int r1i = (tid + 256) >> 2, c1i = (tid + 256) & 3;

    float acc[2][8][4];
#pragma unroll
    for (int mt = 0; mt < 2; mt++)
#pragma unroll
        for (int nt = 0; nt < 8; nt++)
#pragma unroll
            for (int i = 0; i < 4; i++) acc[mt][nt][i] = 0.f;

    uint4 pAh[2], pAl[2], pBh[2], pBl[2];

    auto load_regs = [&](int c) {
        const int k0 = c * 32;
        const __nv_bfloat16* a0 = Ahi + (size_t)(rowBase + r0i) * DIM + k0 + c0i * 8;
        const __nv_bfloat16* a1 = Ahi + (size_t)(rowBase + r1i) * DIM + k0 + c1i * 8;
        const __nv_bfloat16* b0 = Bhi + (size_t)(colBase + r0i) * DIM + k0 + c0i * 8;
        const __nv_bfloat16* b1 = Bhi + (size_t)(colBase + r1i) * DIM + k0 + c1i * 8;
        const size_t dA = g_a_lo - g_a_hi;   // not valid between distinct arrays; use explicit lo ptrs
        (void)dA;
        pAh[0] = *reinterpret_cast<const uint4*>(a0);
        pAh[1] = *reinterpret_cast<const uint4*>(a1);
        pAl[0] = *reinterpret_cast<const uint4*>(Alo + (size_t)(rowBase + r0i) * DIM + k0 + c0i * 8);
        pAl[1] = *reinterpret_cast<const uint4*>(Alo + (size_t)(rowBase + r1i) * DIM + k0 + c1i * 8);
        pBh[0] = *reinterpret_cast<const uint4*>(b0);
        pBh[1] = *reinterpret_cast<const uint4*>(b1);
        pBl[0] = *reinterpret_cast<const uint4*>(Blo + (size_t)(colBase + r0i) * DIM + k0 + c0i * 8);
        pBl[1] = *reinterpret_cast<const uint4*>(Blo + (size_t)(colBase + r1i) * DIM + k0 + c1i * 8);
    };
    auto store_smem = [&]() {
        *reinterpret_cast<uint4*>(&As[0][r0i * SSTRIDE + c0i * 8]) = pAh[0];
        *reinterpret_cast<uint4*>(&As[0][r1i * SSTRIDE + c1i * 8]) = pAh[1];
        *reinterpret_cast<uint4*>(&As[1][r0i * SSTRIDE + c0i * 8]) = pAl[0];
        *reinterpret_cast<uint4*>(&As[1][r1i * SSTRIDE + c1i * 8]) = pAl[1];
        *reinterpret_cast<uint4*>(&Bs[0][r0i * SSTRIDE + c0i * 8]) = pBh[0];
        *reinterpret_cast<uint4*>(&Bs[0][r1i * SSTRIDE + c1i * 8]) = pBh[1];
        *reinterpret_cast<uint4*>(&Bs[1][r0i * SSTRIDE + c0i * 8]) = pBl[0];
        *reinterpret_cast<uint4*>(&Bs[1][r1i * SSTRIDE + c1i * 8]) = pBl[1];
    };

    load_regs(0);
    for (int c = 0; c < DIM / 32; c++) {
        if (c > 0) __syncthreads();
        store_smem();
        __syncthreads();
        if (c < DIM / 32 - 1) load_regs(c + 1);

#pragma unroll
        for (int ks = 0; ks < 2; ks++) {
            unsigned ah[2][4], al[2][4], bh[4][4], bl[4][4];
#pragma unroll
            for (int mt = 0; mt < 2; mt++) {
                ldsm4(ah[mt], aBase + mt * (16 * 80) + ks * 32);
                ldsm4(al[mt], aBase + mt * (16 * 80) + ks * 32 + LOOFF);
            }
#pragma unroll
            for (int nb = 0; nb < 4; nb++) {
                ldsm4(bh[nb], bBase + nb * (16 * 80) + ks * 32);
                ldsm4(bl[nb], bBase + nb * (16 * 80) + ks * 32 + LOOFF);
            }
#pragma unroll
            for (int mt = 0; mt < 2; mt++)
#pragma unroll
                for (int nb = 0; nb < 4; nb++) {
                    mma4(acc[mt][2 * nb + 0], ah[mt], bh[nb][0], bh[nb][2]);
                    mma4(acc[mt][2 * nb + 1], ah[mt], bh[nb][1], bh[nb][3]);
                    mma4(acc[mt][2 * nb + 0], ah[mt], bl[nb][0], bl[nb][2]);
                    mma4(acc[mt][2 * nb + 1], ah[mt], bl[nb][1], bl[nb][3]);
                    mma4(acc[mt][2 * nb + 0], al[mt], bh[nb][0], bh[nb][2]);
                    mma4(acc[mt][2 * nb + 1], al[mt], bh[nb][1], bh[nb][3]);
                }
        }
    }

    // ---- epilogue
#pragma unroll
    for (int mt = 0; mt < 2; mt++)
#pragma unroll
        for (int nb = 0; nb < 4; nb++)
#pragma unroll
            for (int j = 0; j < 2; j++) {
                const float* cc = acc[mt][2 * nb + j];
                const int r   = rowBase + warpM + mt * 16 + gr;
                const int col = colBase + warpN + nb * 16 + j * 8 + qc * 2;
                if (IS_PROJ) {
                    const float b0 = bias[col], b1 = bias[col + 1];
                    *reinterpret_cast<float2*>(&outF[(size_t)(r    ) * ONC + col]) =
                        make_float2(cc[0] + b0, cc[1] + b1);
                    *reinterpret_cast<float2*>(&outF[(size_t)(r + 8) * ONC + col]) =
                        make_float2(cc[2] + b0, cc[3] + b1);
                } else {
                    __nv_bfloat162 h01 = __floats2bfloat162_rn(cc[0], cc[1]);
                    __nv_bfloat162 l01 = __floats2bfloat162_rn(cc[0] - __bfloat162float(h01.x),
                                                               cc[1] - __bfloat162float(h01.y));
                    __nv_bfloat162 h23 = __floats2bfloat162_rn(cc[2], cc[3]);
                    __nv_bfloat162 l23 = __floats2bfloat162_rn(cc[2] - __bfloat162float(h23.x),
                                                               cc[3] - __bfloat162float(h23.y));
                    *reinterpret_cast<__nv_bfloat162*>(&g_c_hi[(size_t)(r    ) * ONC + col]) = h01;
                    *reinterpret_cast<__nv_bfloat162*>(&g_c_lo[(size_t)(r    ) * ONC + col]) = l01;
                    *reinterpret_cast<__nv_bfloat162*>(&g_c_hi[(size_t)(r + 8) * ONC + col]) = h23;
                    *reinterpret_cast<__nv_bfloat162*>(&g_c_lo[(size_t)(r + 8) * ONC + col]) = l23;
                }
            }
}

// ---------------- per-token head-axis attention -----------------------------
__global__ __launch_bounds__(256)
void attn_kernel()
{
    const int warp = threadIdx.x >> 5;
    const int lane = threadIdx.x & 31;
    const int token = blockIdx.x * 8 + warp;
    const size_t cb = (size_t)token * NCAT;

    float qr[8], kr[8], vr[8];
#pragma unroll
    for (int hh = 0; hh < 8; hh++) {
        const int d = hh * 32 + lane;
        qr[hh] = __bfloat162float(g_c_hi[cb +       d]) + __bfloat162float(g_c_lo[cb +       d]);
        kr[hh] = __bfloat162float(g_c_hi[cb + 256 + d]) + __bfloat162float(g_c_lo[cb + 256 + d]);
        vr[hh] = __bfloat162float(g_c_hi[cb + 512 + d]) + __bfloat162float(g_c_lo[cb + 512 + d]);
    }

    const float scale = 0.17677669529663687f;   // 32^-0.5

#pragma unroll
    for (int hh = 0; hh < 8; hh++) {
        float m = -3.0e38f, l = 0.f, acc = 0.f;
#pragma unroll
        for (int g = 0; g < 8; g++) {
            float s = qr[hh] * kr[g];
#pragma unroll
            for (int o = 16; o > 0; o >>= 1)
                s += __shfl_xor_sync(0xffffffffu, s, o);
            s *= scale;
            const float mn   = fmaxf(m, s);
            const float corr = __expf(m - mn);
            const float e    = __expf(s - mn);
            acc = acc * corr + e * vr[g];
            l   = l   * corr + e;
            m   = mn;
        }
        const float val = acc / l;
        const int d = hh * 32 + lane;
        const __nv_bfloat16 hb = __float2bfloat16_rn(val);
        g_x_hi[(size_t)token * DIM + d] = hb;
        g_x_lo[(size_t)token * DIM + d] = __float2bfloat16_rn(val - __bfloat162float(hb));
    }
}

// ---------------------------------------------------------------------------
extern "C" void kernel_launch(void* const* d_in, const int* in_sizes, int n_in,
                              void* d_out, int out_size)
{
    const float* v  = (const float*)d_in[0];
    const float* Wq = (const float*)d_in[1];
    const float* Wk = (const float*)d_in[2];
    const float* Wv = (const float*)d_in[3];
    const float* Wp = (const float*)d_in[4];
    const float* bp = (const float*)d_in[5];
    float* out = (float*)d_out;

    void *pAhi, *pAlo, *pWhi, *pWlo, *pPhi, *pPlo, *pXhi, *pXlo;
    cudaGetSymbolAddress(&pAhi, g_a_hi);
    cudaGetSymbolAddress(&pAlo, g_a_lo);
    cudaGetSymbolAddress(&pWhi, g_w_hi);
    cudaGetSymbolAddress(&pWlo, g_w_lo);
    cudaGetSymbolAddress(&pPhi, g_wp_hi);
    cudaGetSymbolAddress(&pPlo, g_wp_lo);
    cudaGetSymbolAddress(&pXhi, g_x_hi);
    cudaGetSymbolAddress(&pXlo, g_x_lo);

    split_input_kernel<<<NTOK * DIM / 4 / 256, 256>>>(v);
    dim3 tb(32, 8), tg(8, 8);
    transpose_split_kernel<<<tg, tb>>>(Wq, 0);
    transpose_split_kernel<<<tg, tb>>>(Wk, 1);
    transpose_split_kernel<<<tg, tb>>>(Wv, 2);
    transpose_split_kernel<<<tg, tb>>>(Wp, 3);

    dim3 qkv_grid(NTOK / 128, NCAT / 128);   // (512, 6)
    gemm_kernel<NCAT, false><<<qkv_grid, 256>>>(
        (const __nv_bfloat16*)pAhi, (const __nv_bfloat16*)pAlo,
        (const __nv_bfloat16*)pWhi, (const __nv_bfloat16*)pWlo,
        nullptr, nullptr);

    attn_kernel<<<NTOK / 8, 256>>>();

    dim3 proj_grid(NTOK / 128, DIM / 128);   // (512, 2)
    gemm_kernel<DIM, true><<<proj_grid, 256>>>(
        (const __nv_bfloat16*)pXhi, (const __nv_bfloat16*)pXlo,
        (const __nv_bfloat16*)pPhi, (const __nv_bfloat16*)pPlo,
        bp, out);
}

// round 6
// speedup vs baseline: 1.8113x; 1.1538x over previous
#include <cuda_runtime.h>
#include <cuda_bf16.h>
#include <cstdint>
#include <math.h>

// Shapes: B=4,N=128,T=128 -> NTOK=65536 tokens, DIM=256, H=8, hd=32.
#define NTOK 65536
#define DIM  256
#define NCAT 768

// ---------------- device scratch (no allocations allowed) -------------------
__device__ __nv_bfloat16 g_a_hi[NTOK * DIM];
__device__ __nv_bfloat16 g_a_lo[NTOK * DIM];
__device__ __nv_bfloat16 g_w_hi[NCAT * DIM];     // [n][k] transposed cat(Wq,Wk,Wv)
__device__ __nv_bfloat16 g_w_lo[NCAT * DIM];
__device__ __nv_bfloat16 g_wp_hi[DIM * DIM];     // [n][k] transposed Wp
__device__ __nv_bfloat16 g_wp_lo[DIM * DIM];
__device__ __nv_bfloat16 g_c_hi[(size_t)NTOK * NCAT];   // q|k|v per token
__device__ __nv_bfloat16 g_c_lo[(size_t)NTOK * NCAT];
__device__ __nv_bfloat16 g_x_hi[NTOK * DIM];
__device__ __nv_bfloat16 g_x_lo[NTOK * DIM];

// ---------------- helpers ---------------------------------------------------
__device__ __forceinline__ void ldsm4(unsigned* r, unsigned addr) {
    asm volatile("ldmatrix.sync.aligned.m8n8.x4.shared.b16 {%0,%1,%2,%3}, [%4];"
                 : "=r"(r[0]), "=r"(r[1]), "=r"(r[2]), "=r"(r[3]) : "r"(addr));
}
__device__ __forceinline__ void mma4(float* c, const unsigned* a, unsigned b0, unsigned b1) {
    asm volatile(
        "mma.sync.aligned.m16n8k16.row.col.f32.bf16.bf16.f32 "
        "{%0,%1,%2,%3}, {%4,%5,%6,%7}, {%8,%9}, {%0,%1,%2,%3};\n"
        : "+f"(c[0]), "+f"(c[1]), "+f"(c[2]), "+f"(c[3])
        : "r"(a[0]), "r"(a[1]), "r"(a[2]), "r"(a[3]), "r"(b0), "r"(b1));
}
__device__ __forceinline__ uint32_t smem_u32(const void* p) {
    uint32_t a;
    asm("{ .reg .u64 t; cvta.to.shared.u64 t, %1; cvt.u32.u64 %0, t; }" : "=r"(a) : "l"(p));
    return a;
}
#define CP_ASYNC16(dst, src) \
    asm volatile("cp.async.cg.shared.global [%0], [%1], 16;" :: "r"(dst), "l"(src))
#define CP_COMMIT() asm volatile("cp.async.commit_group;" ::: "memory")
#define CP_WAIT1()  asm volatile("cp.async.wait_group 1;" ::: "memory")
#define CP_WAIT0()  asm volatile("cp.async.wait_group 0;" ::: "memory")

// ---------------- pre-pass kernels ------------------------------------------
__global__ __launch_bounds__(256)
void split_input_kernel(const float* __restrict__ v)
{
    const int i = blockIdx.x * 256 + threadIdx.x;
    const float4 x = reinterpret_cast<const float4*>(v)[i];
    __nv_bfloat162 h0 = __floats2bfloat162_rn(x.x, x.y);
    __nv_bfloat162 h1 = __floats2bfloat162_rn(x.z, x.w);
    __nv_bfloat162 l0 = __floats2bfloat162_rn(x.x - __bfloat162float(h0.x),
                                              x.y - __bfloat162float(h0.y));
    __nv_bfloat162 l1 = __floats2bfloat162_rn(x.z - __bfloat162float(h1.x),
                                              x.w - __bfloat162float(h1.y));
    reinterpret_cast<__nv_bfloat162*>(g_a_hi)[i * 2 + 0] = h0;
    reinterpret_cast<__nv_bfloat162*>(g_a_hi)[i * 2 + 1] = h1;
    reinterpret_cast<__nv_bfloat162*>(g_a_lo)[i * 2 + 0] = l0;
    reinterpret_cast<__nv_bfloat162*>(g_a_lo)[i * 2 + 1] = l1;
}

__global__ __launch_bounds__(256)
void transpose_split_kernel(const float* __restrict__ W, int which)
{
    __shared__ float tile[32][33];
    const int tx = threadIdx.x, ty = threadIdx.y;
    const int bx = blockIdx.x, by = blockIdx.y;
#pragma unroll
    for (int j = 0; j < 32; j += 8)
        tile[ty + j][tx] = W[(by * 32 + ty + j) * DIM + bx * 32 + tx];
    __syncthreads();
    __nv_bfloat16* ohi = (which < 3) ? (g_w_hi + which * DIM * DIM) : g_wp_hi;
    __nv_bfloat16* olo = (which < 3) ? (g_w_lo + which * DIM * DIM) : g_wp_lo;
#pragma unroll
    for (int j = 0; j < 32; j += 8) {
        const float val = tile[tx][ty + j];
        const int n = bx * 32 + ty + j;
        const int k = by * 32 + tx;
        const __nv_bfloat16 hb = __float2bfloat16_rn(val);
        ohi[n * DIM + k] = hb;
        olo[n * DIM + k] = __float2bfloat16_rn(val - __bfloat162float(hb));
    }
}

// ---------------- HMMA GEMM with cp.async pipeline --------------------------
// Block tile 128(M) x 128(N), 512 threads = 16 warps as 4M x 4N, warp 32x32.
// K in 8 chunks of 32, double-buffered via cp.async (2-deep pipeline).
// 3-pass bf16 split: ah*bh + ah*bl + al*bh.
//
// Stage layout (per buffer): 4 planes (Ahi, Alo, Bhi, Blo),
// each 128 rows x 32 bf16, row pitch 80 B  -> 10240 B/plane, 40960 B/stage.
#define ROWP   80
#define PLANE  (128 * ROWP)          // 10240
#define STAGE  (4 * PLANE)           // 40960
#define SMEM_GEMM (2 * STAGE)        // 81920

template<int ONC, bool IS_PROJ>
__global__ __launch_bounds__(512, 2)
void gemm_kernel(const __nv_bfloat16* __restrict__ Ahi,
                 const __nv_bfloat16* __restrict__ Alo,
                 const __nv_bfloat16* __restrict__ Bhi,
                 const __nv_bfloat16* __restrict__ Blo,
                 const float* __restrict__ bias,
                 float* __restrict__ outF)
{
    extern __shared__ __align__(128) char smem[];
    const uint32_t sbase = smem_u32(smem);

    const int tid  = threadIdx.x;
    const int warp = tid >> 5;
    const int lane = tid & 31;
    const int lane15 = lane & 15;
    const int laneHi = lane >> 4;
    const int gr = lane >> 2;
    const int qc = lane & 3;
    const int warpM = (warp >> 2) * 32;     // 0,32,64,96
    const int warpN = (warp & 3) * 32;      // 0,32,64,96
    const int colBase = blockIdx.x * 128;   // N fastest -> A-tile L2 reuse
    const int rowBase = blockIdx.y * 128;

    // staging: 512 threads, each 1 16B segment per plane per stage
    const int srow = tid >> 2;              // 0..127
    const int sseg = tid & 3;               // 0..3 (16B each)
    const uint32_t soff = srow * ROWP + sseg * 16;
    const size_t gaOff = (size_t)(rowBase + srow) * DIM + sseg * 8;
    const size_t gbOff = (size_t)(colBase + srow) * DIM + sseg * 8;

    auto issue_stage = [&](int c, int buf) {
        const uint32_t sb = sbase + buf * STAGE + soff;
        const int k0 = c * 32;
        CP_ASYNC16(sb            , Ahi + gaOff + k0);
        CP_ASYNC16(sb + PLANE    , Alo + gaOff + k0);
        CP_ASYNC16(sb + 2 * PLANE, Bhi + gbOff + k0);
        CP_ASYNC16(sb + 3 * PLANE, Blo + gbOff + k0);
        CP_COMMIT();
    };

    float acc[2][4][4];
#pragma unroll
    for (int mt = 0; mt < 2; mt++)
#pragma unroll
        for (int nt = 0; nt < 4; nt++)
#pragma unroll
            for (int i = 0; i < 4; i++) acc[mt][nt][i] = 0.f;

    const uint32_t aBase0 = sbase + (warpM + lane15) * ROWP + laneHi * 16;
    const uint32_t bBase0 = sbase + 2 * PLANE + (warpN + lane15) * ROWP + laneHi * 16;

    issue_stage(0, 0);
    issue_stage(1, 1);

    for (int c = 0; c < 8; c++) {
        const int buf = c & 1;
        CP_WAIT1();
        __syncthreads();

        const uint32_t aB = aBase0 + buf * STAGE;
        const uint32_t bB = bBase0 + buf * STAGE;
#pragma unroll
        for (int ks = 0; ks < 2; ks++) {
            unsigned ah[2][4], al[2][4], bh[2][4], bl[2][4];
#pragma unroll
            for (int mt = 0; mt < 2; mt++) {
                ldsm4(ah[mt], aB + mt * (16 * ROWP) + ks * 32);
                ldsm4(al[mt], aB + mt * (16 * ROWP) + ks * 32 + PLANE);
            }
#pragma unroll
            for (int nb = 0; nb < 2; nb++) {
                ldsm4(bh[nb], bB + nb * (16 * ROWP) + ks * 32);
                ldsm4(bl[nb], bB + nb * (16 * ROWP) + ks * 32 + PLANE);
            }
#pragma unroll
            for (int mt = 0; mt < 2; mt++)
#pragma unroll
                for (int nb = 0; nb < 2; nb++) {
                    mma4(acc[mt][2 * nb + 0], ah[mt], bh[nb][0], bh[nb][2]);
                    mma4(acc[mt][2 * nb + 1], ah[mt], bh[nb][1], bh[nb][3]);
                    mma4(acc[mt][2 * nb + 0], ah[mt], bl[nb][0], bl[nb][2]);
                    mma4(acc[mt][2 * nb + 1], ah[mt], bl[nb][1], bl[nb][3]);
                    mma4(acc[mt][2 * nb + 0], al[mt], bh[nb][0], bh[nb][2]);
                    mma4(acc[mt][2 * nb + 1], al[mt], bh[nb][1], bh[nb][3]);
                }
        }
        __syncthreads();
        if (c + 2 < 8) issue_stage(c + 2, buf);
    }
    CP_WAIT0();

    // ---- epilogue
#pragma unroll
    for (int mt = 0; mt < 2; mt++)
#pragma unroll
        for (int nb = 0; nb < 2; nb++)
#pragma unroll
            for (int j = 0; j < 2; j++) {
                const float* cc = acc[mt][2 * nb + j];
                const int r   = rowBase + warpM + mt * 16 + gr;
                const int col = colBase + warpN + nb * 16 + j * 8 + qc * 2;
                if (IS_PROJ) {
                    const float b0 = bias[col], b1 = bias[col + 1];
                    *reinterpret_cast<float2*>(&outF[(size_t)(r    ) * ONC + col]) =
                        make_float2(cc[0] + b0, cc[1] + b1);
                    *reinterpret_cast<float2*>(&outF[(size_t)(r + 8) * ONC + col]) =
                        make_float2(cc[2] + b0, cc[3] + b1);
                } else {
                    __nv_bfloat162 h01 = __floats2bfloat162_rn(cc[0], cc[1]);
                    __nv_bfloat162 l01 = __floats2bfloat162_rn(cc[0] - __bfloat162float(h01.x),
                                                               cc[1] - __bfloat162float(h01.y));
                    __nv_bfloat162 h23 = __floats2bfloat162_rn(cc[2], cc[3]);
                    __nv_bfloat162 l23 = __floats2bfloat162_rn(cc[2] - __bfloat162float(h23.x),
                                                               cc[3] - __bfloat162float(h23.y));
                    *reinterpret_cast<__nv_bfloat162*>(&g_c_hi[(size_t)(r    ) * ONC + col]) = h01;
                    *reinterpret_cast<__nv_bfloat162*>(&g_c_lo[(size_t)(r    ) * ONC + col]) = l01;
                    *reinterpret_cast<__nv_bfloat162*>(&g_c_hi[(size_t)(r + 8) * ONC + col]) = h23;
                    *reinterpret_cast<__nv_bfloat162*>(&g_c_lo[(size_t)(r + 8) * ONC + col]) = l23;
                }
            }
}

// ---------------- per-token head-axis attention -----------------------------
__global__ __launch_bounds__(256)
void attn_kernel()
{
    const int warp = threadIdx.x >> 5;
    const int lane = threadIdx.x & 31;
    const int token = blockIdx.x * 8 + warp;
    const size_t cb = (size_t)token * NCAT;

    float qr[8], kr[8], vr[8];
#pragma unroll
    for (int hh = 0; hh < 8; hh++) {
        const int d = hh * 32 + lane;
        qr[hh] = __bfloat162float(g_c_hi[cb +       d]) + __bfloat162float(g_c_lo[cb +       d]);
        kr[hh] = __bfloat162float(g_c_hi[cb + 256 + d]) + __bfloat162float(g_c_lo[cb + 256 + d]);
        vr[hh] = __bfloat162float(g_c_hi[cb + 512 + d]) + __bfloat162float(g_c_lo[cb + 512 + d]);
    }

    const float scale = 0.17677669529663687f;   // 32^-0.5

#pragma unroll
    for (int hh = 0; hh < 8; hh++) {
        float m = -3.0e38f, l = 0.f, acc = 0.f;
#pragma unroll
        for (int g = 0; g < 8; g++) {
            float s = qr[hh] * kr[g];
#pragma unroll
            for (int o = 16; o > 0; o >>= 1)
                s += __shfl_xor_sync(0xffffffffu, s, o);
            s *= scale;
            const float mn   = fmaxf(m, s);
            const float corr = __expf(m - mn);
            const float e    = __expf(s - mn);
            acc = acc * corr + e * vr[g];
            l   = l   * corr + e;
            m   = mn;
        }
        const float val = acc / l;
        const int d = hh * 32 + lane;
        const __nv_bfloat16 hb = __float2bfloat16_rn(val);
        g_x_hi[(size_t)token * DIM + d] = hb;
        g_x_lo[(size_t)token * DIM + d] = __float2bfloat16_rn(val - __bfloat162float(hb));
    }
}

// ---------------------------------------------------------------------------
extern "C" void kernel_launch(void* const* d_in, const int* in_sizes, int n_in,
                              void* d_out, int out_size)
{
    const float* v  = (const float*)d_in[0];
    const float* Wq = (const float*)d_in[1];
    const float* Wk = (const float*)d_in[2];
    const float* Wv = (const float*)d_in[3];
    const float* Wp = (const float*)d_in[4];
    const float* bp = (const float*)d_in[5];
    float* out = (float*)d_out;

    void *pAhi, *pAlo, *pWhi, *pWlo, *pPhi, *pPlo, *pXhi, *pXlo;
    cudaGetSymbolAddress(&pAhi, g_a_hi);
    cudaGetSymbolAddress(&pAlo, g_a_lo);
    cudaGetSymbolAddress(&pWhi, g_w_hi);
    cudaGetSymbolAddress(&pWlo, g_w_lo);
    cudaGetSymbolAddress(&pPhi, g_wp_hi);
    cudaGetSymbolAddress(&pPlo, g_wp_lo);
    cudaGetSymbolAddress(&pXhi, g_x_hi);
    cudaGetSymbolAddress(&pXlo, g_x_lo);

    cudaFuncSetAttribute(gemm_kernel<NCAT, false>,
                         cudaFuncAttributeMaxDynamicSharedMemorySize, SMEM_GEMM);
    cudaFuncSetAttribute(gemm_kernel<DIM, true>,
                         cudaFuncAttributeMaxDynamicSharedMemorySize, SMEM_GEMM);

    split_input_kernel<<<NTOK * DIM / 4 / 256, 256>>>(v);
    dim3 tb(32, 8), tg(8, 8);
    transpose_split_kernel<<<tg, tb>>>(Wq, 0);
    transpose_split_kernel<<<tg, tb>>>(Wk, 1);
    transpose_split_kernel<<<tg, tb>>>(Wv, 2);
    transpose_split_kernel<<<tg, tb>>>(Wp, 3);

    dim3 qkv_grid(NCAT / 128, NTOK / 128);   // (6, 512), N fastest
    gemm_kernel<NCAT, false><<<qkv_grid, 512, SMEM_GEMM>>>(
        (const __nv_bfloat16*)pAhi, (const __nv_bfloat16*)pAlo,
        (const __nv_bfloat16*)pWhi, (const __nv_bfloat16*)pWlo,
        nullptr, nullptr);

    attn_kernel<<<NTOK / 8, 256>>>();

    dim3 proj_grid(DIM / 128, NTOK / 128);   // (2, 512)
    gemm_kernel<DIM, true><<<proj_grid, 512, SMEM_GEMM>>>(
        (const __nv_bfloat16*)pXhi, (const __nv_bfloat16*)pXlo,
        (const __nv_bfloat16*)pPhi, (const __nv_bfloat16*)pPlo,
        bp, out);
}